// round 14
// baseline (speedup 1.0000x reference)
#include <cuda_runtime.h>
#include <cuda_fp16.h>
#include <cstdint>

// Problem constants
#define NN 100000   // nodes
#define NH 50000    // hyperedges
#define NI 600000   // incidences
#define DH 128
#define NC 40

// ---------------- scratch (device globals) -----------------------------------
__device__ __align__(128) __half g_x0h   [NN * DH];
__device__ __align__(128) __half g_x1h   [NH * DH];
__device__ __align__(128) __half g_m0h   [NN * DH];
__device__ __align__(128) __half g_m0heA [NH * DH];   // L0 he-aggregate
__device__ __align__(128) __half g_m0heB [NH * DH];   // L1 he-aggregate
__device__ __align__(128) __half g_m1h   [NH * DH];
__device__ __align__(128) __half g_m1nh  [NN * DH];   // node-aggregate (reused)
__device__ __align__(128) __half g_wt    [131072];    // transposed fp16 weights

// CSR scratch (both directions)
__device__ int   g_cnt_he[NH];
__device__ int   g_off_he[NH + 1];
__device__ int   g_cur_he[NH];
__device__ int   g_src_he[NI];
__device__ float g_w_he  [NI];
__device__ int   g_cnt_nn[NN];
__device__ int   g_off_nn[NN + 1];
__device__ int   g_cur_nn[NN];
__device__ int   g_src_nn[NI];
__device__ float g_w_nn  [NI];
__device__ int   g_bsum_he[128];
__device__ int   g_bsum_nn[128];

#define WT_ENC  0          // 128 x 256
#define WT_MSG0 32768      // 2 x (128 x 128)
#define WT_MSG1 65536      // 2 x (128 x 256)

__device__ __forceinline__ float sigm(float x) {
    return 1.0f / (1.0f + __expf(-x));
}

__device__ __forceinline__ void mma_f16(float (&d)[4], const uint32_t (&a)[4],
                                        const uint32_t (&b)[2]) {
    asm volatile(
        "mma.sync.aligned.m16n8k16.row.col.f32.f16.f16.f32 "
        "{%0,%1,%2,%3}, {%4,%5,%6,%7}, {%8,%9}, {%0,%1,%2,%3};"
        : "+f"(d[0]), "+f"(d[1]), "+f"(d[2]), "+f"(d[3])
        : "r"(a[0]), "r"(a[1]), "r"(a[2]), "r"(a[3]), "r"(b[0]), "r"(b[1]));
}

__device__ __forceinline__ void ldsm4(uint32_t (&r)[4], uint32_t addr) {
    asm volatile("ldmatrix.sync.aligned.m8n8.x4.shared.b16 {%0,%1,%2,%3}, [%4];"
        : "=r"(r[0]), "=r"(r[1]), "=r"(r[2]), "=r"(r[3]) : "r"(addr));
}

__device__ __forceinline__ void cp16(uint32_t dst, const void* src) {
    asm volatile("cp.async.cg.shared.global [%0], [%1], 16;"
                 :: "r"(dst), "l"(src));
}
__device__ __forceinline__ void cp16s(uint32_t dst, const void* src, int sz) {
    asm volatile("cp.async.cg.shared.global [%0], [%1], 16, %2;"
                 :: "r"(dst), "l"(src), "r"(sz));
}

// SMEM geometry: 3 stages, A and B tiles 128 rows x 32 halves, row stride 40 halves
#define STAGES 3
#define ASTR 40
#define STAGE_B (128 * ASTR * 2)            // 10240 bytes
#define SMEM_BYTES (STAGES * 2 * STAGE_B)   // 61440 bytes

// =================== MMA core =================================================
struct GemmCtx {
    uint32_t as0, bs0;
    int tid, lane, wid, wm, wn, block_row;
    uint32_t aaddr[2], baddr[4];
};

__device__ __forceinline__ void gemm_init(GemmCtx& g, uint32_t smem_u32,
                                          int block_row) {
    g.as0 = smem_u32;
    g.bs0 = smem_u32 + STAGES * STAGE_B;
    g.tid  = threadIdx.x;
    g.lane = g.tid & 31;
    g.wid  = g.tid >> 5;
    g.wm   = g.wid & 3;
    g.wn   = g.wid >> 2;
    g.block_row = block_row;
    const int arow_f = ((g.lane >> 3) & 1) * 8 + (g.lane & 7);
    const int akk_f  = (g.lane >> 4) * 8;
    const int brow_f = (g.lane >> 4) * 8 + (g.lane & 7);
    const int bkk_f  = ((g.lane >> 3) & 1) * 8;
    #pragma unroll
    for (int mi = 0; mi < 2; mi++)
        g.aaddr[mi] = g.as0 + ((g.wm * 32 + mi * 16 + arow_f) * ASTR + akk_f) * 2;
    #pragma unroll
    for (int nj = 0; nj < 4; nj++)
        g.baddr[nj] = g.bs0 + ((g.wn * 64 + nj * 16 + brow_f) * ASTR + bkk_f) * 2;
}

__device__ __forceinline__ void gemm_mma_chunk(const GemmCtx& g, int s,
                                               float (&acc)[2][8][4]) {
    #pragma unroll
    for (int ks = 0; ks < 2; ks++) {
        const uint32_t koff = s * STAGE_B + ks * 32;
        uint32_t af[2][4];
        ldsm4(af[0], g.aaddr[0] + koff);
        ldsm4(af[1], g.aaddr[1] + koff);
        uint32_t bf[4][4];
        #pragma unroll
        for (int nj = 0; nj < 4; nj++) ldsm4(bf[nj], g.baddr[nj] + koff);
        #pragma unroll
        for (int mi = 0; mi < 2; mi++)
            #pragma unroll
            for (int ni = 0; ni < 8; ni++) {
                uint32_t b[2] = { bf[ni >> 1][(ni & 1) * 2],
                                  bf[ni >> 1][(ni & 1) * 2 + 1] };
                mma_f16(acc[mi][ni], af[mi], b);
            }
    }
}

template<bool SIG>
__device__ __forceinline__ void gemm_epilogue_h(const GemmCtx& g, float (&acc)[2][8][4],
                                                const float* __restrict__ bias,
                                                __half* __restrict__ C, int M) {
    const int lr = g.lane >> 2, lc = g.lane & 3;
    #pragma unroll
    for (int mi = 0; mi < 2; mi++) {
        const int r0 = g.block_row + g.wm * 32 + mi * 16 + lr;
        #pragma unroll
        for (int ni = 0; ni < 8; ni++) {
            const int col = g.wn * 64 + ni * 8 + 2 * lc;
            const float b0 = bias[col], b1 = bias[col + 1];
            float v0 = acc[mi][ni][0] + b0;
            float v1 = acc[mi][ni][1] + b1;
            float v2 = acc[mi][ni][2] + b0;
            float v3 = acc[mi][ni][3] + b1;
            if (SIG) { v0 = sigm(v0); v1 = sigm(v1); v2 = sigm(v2); v3 = sigm(v3); }
            __half2 h01 = __floats2half2_rn(v0, v1);
            __half2 h23 = __floats2half2_rn(v2, v3);
            if (r0 < M)     *(__half2*)(C + (size_t)r0 * 128 + col) = h01;
            if (r0 + 8 < M) *(__half2*)(C + (size_t)(r0 + 8) * 128 + col) = h23;
        }
    }
}

// ---------------- fp16 GEMM with optional fused residual update --------------
// C[M,128] = sigm( A[M,KTOT] @ Wt^T + bias )
// Non-FUSE: A cols [0,128) from A0, [128,KTOT) from A1 (both fp16, cp.async).
// FUSE:     A cols [0,128) = sigm(A0 + Madd)  (both fp16, depth-2 staged LDG;
//           written back to Awb if WB), cols [128,KTOT) from A1 via cp.async.
template<int KTOT, bool FUSE, bool WB>
__global__ __launch_bounds__(256, 2)
void gemm_h(const __half* __restrict__ A0,
            const __half* __restrict__ A1,
            const __half* __restrict__ Madd,
            __half* __restrict__ Awb,
            const __half* __restrict__ Wt,
            const float* __restrict__ bias,
            __half* __restrict__ C, int M)
{
    extern __shared__ __half smem[];
    uint32_t smem_u32;
    asm("{ .reg .u64 t; cvta.to.shared.u64 t, %1; cvt.u32.u64 %0, t; }"
        : "=r"(smem_u32) : "l"(smem));
    GemmCtx g;
    gemm_init(g, smem_u32, blockIdx.x * 128);
    constexpr int NCHUNK = KTOT / 32;
    constexpr int NFUSE  = FUSE ? 4 : 0;   // FUSE chunks are 0..3 (cols < 128)

    float acc[2][8][4];
    #pragma unroll
    for (int mi = 0; mi < 2; mi++)
        #pragma unroll
        for (int ni = 0; ni < 8; ni++)
            #pragma unroll
            for (int j = 0; j < 4; j++) acc[mi][ni][j] = 0.0f;

    uint4 px[2][2], pmh[2][2];   // [buf][i]

    auto ldgA = [&](int c, int buf) {
        if (!FUSE || c >= NFUSE) return;
        #pragma unroll
        for (int i = 0; i < 2; i++) {
            const int idx = g.tid + i * 256;
            const int row = idx >> 2, seg = idx & 3;
            const int grow = g.block_row + row;
            const int col = c * 32 + seg * 8;
            if (grow < M) {
                px[buf][i]  = *(const uint4*)(A0 + (size_t)grow * 128 + col);
                pmh[buf][i] = *(const uint4*)(Madd + (size_t)grow * 128 + col);
            } else {
                px[buf][i] = pmh[buf][i] = make_uint4(0, 0, 0, 0);
            }
        }
    };
    auto stsA = [&](int c, int s, int buf) {
        if (!FUSE || c >= NFUSE) return;
        #pragma unroll
        for (int i = 0; i < 2; i++) {
            const int idx = g.tid + i * 256;
            const int row = idx >> 2, seg = idx & 3;
            const int grow = g.block_row + row;
            const int col = c * 32 + seg * 8;
            const __half2* hx = reinterpret_cast<const __half2*>(&px[buf][i]);
            const __half2* hm = reinterpret_cast<const __half2*>(&pmh[buf][i]);
            uint4 h;
            uint32_t* hp = reinterpret_cast<uint32_t*>(&h);
            #pragma unroll
            for (int j = 0; j < 4; j++) {
                float2 fx = __half22float2(hx[j]);
                float2 fm = __half22float2(hm[j]);
                __half2 u = __floats2half2_rn(sigm(fx.x + fm.x), sigm(fx.y + fm.y));
                hp[j] = *reinterpret_cast<uint32_t*>(&u);
            }
            const uint32_t dst = g.as0 + s * STAGE_B + (row * ASTR + seg * 8) * 2;
            asm volatile("st.shared.v4.b32 [%0], {%1,%2,%3,%4};"
                         :: "r"(dst), "r"(h.x), "r"(h.y), "r"(h.z), "r"(h.w));
            if (WB && grow < M)
                *(uint4*)(Awb + (size_t)grow * 128 + col) = h;
        }
    };
    auto cpA = [&](int c, int s) {
        if (FUSE && c < NFUSE) return;
        const int gk = c * 32;
        #pragma unroll
        for (int i = 0; i < 2; i++) {
            const int idx = g.tid + i * 256;
            const int row = idx >> 2, seg = idx & 3;
            const int grow = g.block_row + row;
            const int col = gk + seg * 8;
            const __half* src = (col < 128)
                ? A0 + (size_t)grow * 128 + col
                : A1 + (size_t)grow * 128 + (col - 128);
            const uint32_t dst = g.as0 + s * STAGE_B + (row * ASTR + seg * 8) * 2;
            cp16s(dst, grow < M ? (const void*)src : (const void*)Wt, grow < M ? 16 : 0);
        }
    };
    auto cpB = [&](int c, int s) {
        const int k0 = c * 32;
        #pragma unroll
        for (int i = 0; i < 2; i++) {
            const int idx = g.tid + i * 256;
            const int row = idx >> 2, seg = idx & 3;
            const uint32_t dst = g.bs0 + s * STAGE_B + (row * ASTR + seg * 8) * 2;
            cp16(dst, Wt + (size_t)row * KTOT + k0 + seg * 8);
        }
    };

    ldgA(0, 0);
    ldgA(1, 1);
    cpA(0, 0); cpB(0, 0);
    asm volatile("cp.async.commit_group;");

    for (int c = 0; c < NCHUNK; c++) {
        const int s = c % 3;
        stsA(c, s, c & 1);
        ldgA(c + 2, c & 1);
        if (c + 1 < NCHUNK) {
            cpA(c + 1, (c + 1) % 3);
            cpB(c + 1, (c + 1) % 3);
            asm volatile("cp.async.commit_group;");
            asm volatile("cp.async.wait_group 1;");
        } else {
            asm volatile("cp.async.wait_group 0;");
        }
        __syncthreads();
        gemm_mma_chunk(g, s, acc);
    }
    gemm_epilogue_h<true>(g, acc, bias, C, M);
}

// ---------------- merged encode GEMM: both x_0 and x_1 in one launch ---------
#define GNN ((NN + 127) / 128)
#define GNH ((NH + 127) / 128)

__global__ __launch_bounds__(256, 2)
void gemm_enc2(const float* __restrict__ A_node,   // [NN,256] fp32
               const float* __restrict__ A_he,     // [NH,256] fp32
               const __half* __restrict__ Wt,      // [128][256]
               const float* __restrict__ bias,
               __half* __restrict__ C_node,
               __half* __restrict__ C_he)
{
    const bool isHE = blockIdx.x >= GNN;
    const int  bidx = isHE ? blockIdx.x - GNN : blockIdx.x;
    const float*  A = isHE ? A_he : A_node;
    __half*       C = isHE ? C_he : C_node;
    const int     M = isHE ? NH : NN;

    extern __shared__ __half smem[];
    uint32_t smem_u32;
    asm("{ .reg .u64 t; cvta.to.shared.u64 t, %1; cvt.u32.u64 %0, t; }"
        : "=r"(smem_u32) : "l"(smem));
    GemmCtx g;
    gemm_init(g, smem_u32, bidx * 128);
    constexpr int NCHUNK = 8;   // KTOT = 256

    const int arow = g.tid >> 1;
    const int aseg = g.tid & 1;
    const int grow = g.block_row + arow;

    float acc[2][8][4];
    #pragma unroll
    for (int mi = 0; mi < 2; mi++)
        #pragma unroll
        for (int ni = 0; ni < 8; ni++)
            #pragma unroll
            for (int j = 0; j < 4; j++) acc[mi][ni][j] = 0.0f;

    // depth-2 register prefetch for A (DRAM latency cover)
    float4 pa[2][4];
    auto ldgA = [&](int c, int buf) {
        const int gcol = c * 32 + aseg * 16;
        if (grow < M) {
            const float* p = A + (size_t)grow * 256 + gcol;
            #pragma unroll
            for (int j = 0; j < 4; j++) pa[buf][j] = *(const float4*)(p + 4 * j);
        } else {
            #pragma unroll
            for (int j = 0; j < 4; j++) pa[buf][j] = make_float4(0.f, 0.f, 0.f, 0.f);
        }
    };
    auto stsA = [&](int s, int buf) {
        uint32_t h[8];
        #pragma unroll
        for (int j = 0; j < 4; j++) {
            __half2 h0 = __floats2half2_rn(pa[buf][j].x, pa[buf][j].y);
            __half2 h1 = __floats2half2_rn(pa[buf][j].z, pa[buf][j].w);
            h[2 * j]     = *reinterpret_cast<uint32_t*>(&h0);
            h[2 * j + 1] = *reinterpret_cast<uint32_t*>(&h1);
        }
        const uint32_t dst = g.as0 + s * STAGE_B + (arow * ASTR + aseg * 16) * 2;
        asm volatile("st.shared.v4.b32 [%0], {%1,%2,%3,%4};"
                     :: "r"(dst), "r"(h[0]), "r"(h[1]), "r"(h[2]), "r"(h[3]));
        asm volatile("st.shared.v4.b32 [%0], {%1,%2,%3,%4};"
                     :: "r"(dst + 16), "r"(h[4]), "r"(h[5]), "r"(h[6]), "r"(h[7]));
    };
    auto cpB = [&](int c, int s) {
        const int k0 = c * 32;
        #pragma unroll
        for (int i = 0; i < 2; i++) {
            const int idx = g.tid + i * 256;
            const int row = idx >> 2, seg = idx & 3;
            const uint32_t dst = g.bs0 + s * STAGE_B + (row * ASTR + seg * 8) * 2;
            cp16(dst, Wt + (size_t)row * 256 + k0 + seg * 8);
        }
    };

    ldgA(0, 0);
    ldgA(1, 1);
    cpB(0, 0);
    asm volatile("cp.async.commit_group;");

    for (int c = 0; c < NCHUNK; c++) {
        const int s = c % 3;
        stsA(s, c & 1);
        if (c + 2 < NCHUNK) ldgA(c + 2, c & 1);
        if (c + 1 < NCHUNK) {
            cpB(c + 1, (c + 1) % 3);
            asm volatile("cp.async.commit_group;");
            asm volatile("cp.async.wait_group 1;");
        } else {
            asm volatile("cp.async.wait_group 0;");
        }
        __syncthreads();
        gemm_mma_chunk(g, s, acc);
    }
    gemm_epilogue_h<false>(g, acc, bias, C, M);
}

// ---------------- weight transpose+convert ------------------------------------
__device__ __forceinline__ void wtrans_body(const float* W, __half* Wt, int K,
                                            int kb, int nb)
{
    __shared__ float tile[32][33];
    const int tx = threadIdx.x, ty = threadIdx.y;
    #pragma unroll
    for (int i = 0; i < 32; i += 8)
        tile[ty + i][tx] = W[(size_t)(kb + ty + i) * 128 + nb + tx];
    __syncthreads();
    #pragma unroll
    for (int i = 0; i < 32; i += 8)
        Wt[(size_t)(nb + ty + i) * K + kb + tx] = __float2half(tile[tx][ty + i]);
}

__global__ void wtrans_enc(const float* __restrict__ W_enc, __half* __restrict__ wt)
{
    wtrans_body(W_enc, wt + WT_ENC, 256, blockIdx.x * 32, blockIdx.y * 32);
}

__global__ void wtrans_msg(const float* __restrict__ W_msg0,
                           const float* __restrict__ W_msg1,
                           __half* __restrict__ wt)
{
    const float* W; __half* Wt; int K;
    switch (blockIdx.z) {
        case 0: W = W_msg0;          Wt = wt + WT_MSG0;          K = 128; break;
        case 1: W = W_msg0 + 16384;  Wt = wt + WT_MSG0 + 16384;  K = 128; break;
        case 2: W = W_msg1;          Wt = wt + WT_MSG1;          K = 256; break;
        default:W = W_msg1 + 32768;  Wt = wt + WT_MSG1 + 32768;  K = 256; break;
    }
    const int kb = blockIdx.x * 32;
    if (kb >= K) return;
    wtrans_body(W, Wt, K, kb, blockIdx.y * 32);
}

// ---------------- output GEMM: C[M,40] = sigm(Ah+Mx) @ W[128,40] + bias ------
__global__ __launch_bounds__(256)
void gemm_out(const __half* __restrict__ Ah, const __half* __restrict__ Mx,
              const float* __restrict__ W,
              const float* __restrict__ bias, float* __restrict__ C, int M)
{
    __shared__ float Ws[128][40];
    __shared__ float Asm[32][132];

    const int tid = threadIdx.x;
    const int row0 = blockIdx.x * 32;

    for (int i = tid; i < 128 * 40; i += 256)
        Ws[i / 40][i % 40] = W[i];

    for (int i = tid; i < 32 * 32; i += 256) {
        int r = i >> 5, c = (i & 31) * 4;
        float4 v = make_float4(0.f, 0.f, 0.f, 0.f);
        if (row0 + r < M) {
            uint2 hv = *(const uint2*)(Ah + (size_t)(row0 + r) * 128 + c);
            uint2 mv = *(const uint2*)(Mx + (size_t)(row0 + r) * 128 + c);
            float2 f0 = __half22float2(*(const __half2*)&hv.x);
            float2 f1 = __half22float2(*(const __half2*)&hv.y);
            float2 m0 = __half22float2(*(const __half2*)&mv.x);
            float2 m1 = __half22float2(*(const __half2*)&mv.y);
            v.x = sigm(f0.x + m0.x); v.y = sigm(f0.y + m0.y);
            v.z = sigm(f1.x + m1.x); v.w = sigm(f1.y + m1.y);
        }
        Asm[r][c + 0] = v.x; Asm[r][c + 1] = v.y; Asm[r][c + 2] = v.z; Asm[r][c + 3] = v.w;
    }
    __syncthreads();

    const int r  = tid >> 3;
    const int c0 = (tid & 7) * 5;
    float acc[5];
    #pragma unroll
    for (int j = 0; j < 5; j++) acc[j] = bias[c0 + j];

    for (int k = 0; k < 128; k++) {
        float a = Asm[r][k];
        #pragma unroll
        for (int j = 0; j < 5; j++) acc[j] += a * Ws[k][c0 + j];
    }

    if (row0 + r < M) {
        #pragma unroll
        for (int j = 0; j < 5; j++)
            C[(size_t)(row0 + r) * 40 + c0 + j] = acc[j];
    }
}

// ---------------- CSR build (both directions fused) --------------------------
__global__ void hist2(const int* __restrict__ he, const int* __restrict__ nn,
                      int* __restrict__ cnt_he, int* __restrict__ cnt_nn, int n)
{
    int i = blockIdx.x * blockDim.x + threadIdx.x;
    if (i < n) {
        atomicAdd(&cnt_he[__ldg(he + i)], 1);
        atomicAdd(&cnt_nn[__ldg(nn + i)], 1);
    }
}

__device__ __forceinline__ void scan_blk_body(const int* cnt, int* off, int* bsum,
                                              int n, int bid)
{
    __shared__ int wsum[8];
    const int tid  = threadIdx.x;
    const int lane = tid & 31;
    const int base = bid * 2048 + tid * 8;

    int v[8];
    #pragma unroll
    for (int j = 0; j < 8; j++) v[j] = (base + j < n) ? __ldg(cnt + base + j) : 0;
    int s = 0;
    #pragma unroll
    for (int j = 0; j < 8; j++) { int t = v[j]; v[j] = s; s += t; }

    int ws = s;
    #pragma unroll
    for (int d = 1; d < 32; d <<= 1) {
        int t = __shfl_up_sync(0xffffffffu, ws, d);
        if (lane >= d) ws += t;
    }
    if (lane == 31) wsum[tid >> 5] = ws;
    __syncthreads();
    if (tid < 8) {
        int t = wsum[tid];
        int acc = t;
        #pragma unroll
        for (int d = 1; d < 8; d <<= 1) {
            int u = __shfl_up_sync(0xffu, acc, d);
            if (tid >= d) acc += u;
        }
        wsum[tid] = acc - t;
    }
    __syncthreads();

    const int thread_excl = (ws - s) + wsum[tid >> 5];
    #pragma unroll
    for (int j = 0; j < 8; j++)
        if (base + j < n) off[base + j] = thread_excl + v[j];
    if (tid == 255) bsum[bid] = thread_excl + s;
}

#define SB_HE ((NH + 2047) / 2048)   // 25
#define SB_NN ((NN + 2047) / 2048)   // 49

__global__ __launch_bounds__(256)
void scan_blk_both(const int* __restrict__ cnt_he, int* __restrict__ off_he,
                   int* __restrict__ bsum_he,
                   const int* __restrict__ cnt_nn, int* __restrict__ off_nn,
                   int* __restrict__ bsum_nn)
{
    if (blockIdx.x < SB_HE)
        scan_blk_body(cnt_he, off_he, bsum_he, NH, blockIdx.x);
    else
        scan_blk_body(cnt_nn, off_nn, bsum_nn, NN, blockIdx.x - SB_HE);
}

__global__ __launch_bounds__(128)
void scan_bsum2(int* __restrict__ bsum_he, int* __restrict__ bsum_nn)
{
    __shared__ int sm[128];
    int* b = (blockIdx.x == 0) ? bsum_he : bsum_nn;
    const int nb = (blockIdx.x == 0) ? SB_HE : SB_NN;
    const int tid = threadIdx.x;
    int v = (tid < nb) ? b[tid] : 0;
    sm[tid] = v;
    __syncthreads();
    for (int d = 1; d < 128; d <<= 1) {
        int t = (tid >= d) ? sm[tid - d] : 0;
        __syncthreads();
        sm[tid] += t;
        __syncthreads();
    }
    if (tid < nb) b[tid] = sm[tid] - v;
}

__global__ void scan_add_both(int* __restrict__ off_he, int* __restrict__ cur_he,
                              const int* __restrict__ bsum_he,
                              int* __restrict__ off_nn, int* __restrict__ cur_nn,
                              const int* __restrict__ bsum_nn)
{
    int i = blockIdx.x * blockDim.x + threadIdx.x;
    if (i < NH) {
        int v = off_he[i] + __ldg(bsum_he + (i >> 11));
        off_he[i] = v;
        cur_he[i] = v;
        if (i == 0) off_he[NH] = NI;
    } else if (i < NH + NN) {
        int j = i - NH;
        int v = off_nn[j] + __ldg(bsum_nn + (j >> 11));
        off_nn[j] = v;
        cur_nn[j] = v;
        if (j == 0) off_nn[NN] = NI;
    }
}

__global__ void fill2(const int* __restrict__ he, const int* __restrict__ nn,
                      const float* __restrict__ w,
                      int* __restrict__ cur_he, int* __restrict__ src_he,
                      float* __restrict__ w_he,
                      int* __restrict__ cur_nn, int* __restrict__ src_nn,
                      float* __restrict__ w_nn, int n)
{
    int i = blockIdx.x * blockDim.x + threadIdx.x;
    if (i >= n) return;
    const int h = __ldg(he + i);
    const int v = __ldg(nn + i);
    const float wv = __ldg(w + i);
    int p = atomicAdd(&cur_he[h], 1);
    src_he[p] = v;
    w_he[p]   = wv;
    int q = atomicAdd(&cur_nn[v], 1);
    src_nn[q] = h;
    w_nn[q]   = wv;
}

// ---------------- segment-sum SpMM: dst16 = sum_e w_e * src[csrc[e]] ---------
__global__ __launch_bounds__(256)
void spmm_kernel(const __half* __restrict__ src,
                 const int*    __restrict__ csrc,
                 const float*  __restrict__ cw,
                 const int*    __restrict__ off,
                 __half* __restrict__ dst16, int nrows)
{
    const int warp = (blockIdx.x * 256 + threadIdx.x) >> 5;
    const int lane = threadIdx.x & 31;
    if (warp >= nrows) return;

    const int s = __ldg(off + warp);
    const int e = __ldg(off + warp + 1);

    float a0 = 0.f, a1 = 0.f, a2 = 0.f, a3 = 0.f;
    int i = s;
    for (; i + 3 < e; i += 4) {
        int   n0 = __ldg(csrc + i),     n1 = __ldg(csrc + i + 1);
        int   n2 = __ldg(csrc + i + 2), n3 = __ldg(csrc + i + 3);
        float w0 = __ldg(cw + i),     w1 = __ldg(cw + i + 1);
        float w2 = __ldg(cw + i + 2), w3 = __ldg(cw + i + 3);
        uint2 p0 = *(const uint2*)(src + (size_t)n0 * 128 + lane * 4);
        uint2 p1 = *(const uint2*)(src + (size_t)n1 * 128 + lane * 4);
        uint2 p2 = *(const uint2*)(src + (size_t)n2 * 128 + lane * 4);
        uint2 p3 = *(const uint2*)(src + (size_t)n3 * 128 + lane * 4);
        float2 f0a = __half22float2(*(const __half2*)&p0.x);
        float2 f0b = __half22float2(*(const __half2*)&p0.y);
        float2 f1a = __half22float2(*(const __half2*)&p1.x);
        float2 f1b = __half22float2(*(const __half2*)&p1.y);
        float2 f2a = __half22float2(*(const __half2*)&p2.x);
        float2 f2b = __half22float2(*(const __half2*)&p2.y);
        float2 f3a = __half22float2(*(const __half2*)&p3.x);
        float2 f3b = __half22float2(*(const __half2*)&p3.y);
        a0 += w0 * f0a.x + w1 * f1a.x + w2 * f2a.x + w3 * f3a.x;
        a1 += w0 * f0a.y + w1 * f1a.y + w2 * f2a.y + w3 * f3a.y;
        a2 += w0 * f0b.x + w1 * f1b.x + w2 * f2b.x + w3 * f3b.x;
        a3 += w0 * f0b.y + w1 * f1b.y + w2 * f2b.y + w3 * f3b.y;
    }
    for (; i < e; i++) {
        const int   n0 = __ldg(csrc + i);
        const float w0 = __ldg(cw + i);
        const uint2 p0 = *(const uint2*)(src + (size_t)n0 * 128 + lane * 4);
        float2 f00 = __half22float2(*(const __half2*)&p0.x);
        float2 f01 = __half22float2(*(const __half2*)&p0.y);
        a0 += w0 * f00.x; a1 += w0 * f00.y;
        a2 += w0 * f01.x; a3 += w0 * f01.y;
    }
    __half2 h01 = __floats2half2_rn(a0, a1);
    __half2 h23 = __floats2half2_rn(a2, a3);
    uint2 u;
    u.x = *reinterpret_cast<uint32_t*>(&h01);
    u.y = *reinterpret_cast<uint32_t*>(&h23);
    *(uint2*)(dst16 + (size_t)warp * 128 + lane * 4) = u;
}

// ---------------- host driver ------------------------------------------------
extern "C" void kernel_launch(void* const* d_in, const int* in_sizes, int n_in,
                              void* d_out, int out_size)
{
    const float* x_0      = (const float*)d_in[0];
    const float* x_1      = (const float*)d_in[1];
    const int*   node_idx = (const int*)  d_in[2];
    const int*   he_idx   = (const int*)  d_in[3];
    const float* inc_vals = (const float*)d_in[4];
    const float* W_enc    = (const float*)d_in[5];
    const float* b_enc    = (const float*)d_in[6];
    const float* W_msg0   = (const float*)d_in[7];
    const float* b_msg0   = (const float*)d_in[8];
    const float* W_msg1   = (const float*)d_in[9];
    const float* b_msg1   = (const float*)d_in[10];
    const float* W_out    = (const float*)d_in[11];
    const float* b_out    = (const float*)d_in[12];
    float* out = (float*)d_out;

    __half *x0h, *x1h, *m0h, *m0heA, *m0heB, *m1h, *m1nh, *wt;
    int *cnt_he, *off_he, *cur_he, *src_he;
    int *cnt_nn, *off_nn, *cur_nn, *src_nn;
    int *bsum_he, *bsum_nn;
    float *w_he, *w_nn;
    cudaGetSymbolAddress((void**)&x0h,     g_x0h);
    cudaGetSymbolAddress((void**)&x1h,     g_x1h);
    cudaGetSymbolAddress((void**)&m0h,     g_m0h);
    cudaGetSymbolAddress((void**)&m0heA,   g_m0heA);
    cudaGetSymbolAddress((void**)&m0heB,   g_m0heB);
    cudaGetSymbolAddress((void**)&m1h,     g_m1h);
    cudaGetSymbolAddress((void**)&m1nh,    g_m1nh);
    cudaGetSymbolAddress((void**)&wt,      g_wt);
    cudaGetSymbolAddress((void**)&cnt_he,  g_cnt_he);
    cudaGetSymbolAddress((void**)&off_he,  g_off_he);
    cudaGetSymbolAddress((void**)&cur_he,  g_cur_he);
    cudaGetSymbolAddress((void**)&src_he,  g_src_he);
    cudaGetSymbolAddress((void**)&w_he,    g_w_he);
    cudaGetSymbolAddress((void**)&cnt_nn,  g_cnt_nn);
    cudaGetSymbolAddress((void**)&off_nn,  g_off_nn);
    cudaGetSymbolAddress((void**)&cur_nn,  g_cur_nn);
    cudaGetSymbolAddress((void**)&src_nn,  g_src_nn);
    cudaGetSymbolAddress((void**)&w_nn,    g_w_nn);
    cudaGetSymbolAddress((void**)&bsum_he, g_bsum_he);
    cudaGetSymbolAddress((void**)&bsum_nn, g_bsum_nn);

    static cudaStream_t s_csr = nullptr;
    static cudaEvent_t evFork = nullptr, evCsr = nullptr, evWt = nullptr;
    static int smem_set = 0;
    if (!smem_set) {
        cudaFuncSetAttribute(gemm_enc2,
                             cudaFuncAttributeMaxDynamicSharedMemorySize, SMEM_BYTES);
        cudaFuncSetAttribute(gemm_h<128, false, false>,
                             cudaFuncAttributeMaxDynamicSharedMemorySize, SMEM_BYTES);
        cudaFuncSetAttribute(gemm_h<256, false, false>,
                             cudaFuncAttributeMaxDynamicSharedMemorySize, SMEM_BYTES);
        cudaFuncSetAttribute(gemm_h<128, true, true>,
                             cudaFuncAttributeMaxDynamicSharedMemorySize, SMEM_BYTES);
        cudaFuncSetAttribute(gemm_h<256, true, false>,
                             cudaFuncAttributeMaxDynamicSharedMemorySize, SMEM_BYTES);
        cudaStreamCreateWithFlags(&s_csr, cudaStreamNonBlocking);
        cudaEventCreateWithFlags(&evFork, cudaEventDisableTiming);
        cudaEventCreateWithFlags(&evCsr,  cudaEventDisableTiming);
        cudaEventCreateWithFlags(&evWt,   cudaEventDisableTiming);
        smem_set = 1;
    }

    const int gEdge = (NI + 255) / 256;

    // ---------------- fork: msg-weight transpose + CSR build on side stream --
    cudaEventRecord(evFork, 0);
    cudaStreamWaitEvent(s_csr, evFork, 0);
    wtrans_msg<<<dim3(8, 4, 4), dim3(32, 8), 0, s_csr>>>(W_msg0, W_msg1, wt);
    cudaEventRecord(evWt, s_csr);
    cudaMemsetAsync(cnt_he, 0, NH * sizeof(int), s_csr);
    cudaMemsetAsync(cnt_nn, 0, NN * sizeof(int), s_csr);
    hist2<<<gEdge, 256, 0, s_csr>>>(he_idx, node_idx, cnt_he, cnt_nn, NI);
    scan_blk_both<<<SB_HE + SB_NN, 256, 0, s_csr>>>(cnt_he, off_he, bsum_he,
                                                    cnt_nn, off_nn, bsum_nn);
    scan_bsum2<<<2, 128, 0, s_csr>>>(bsum_he, bsum_nn);
    scan_add_both<<<(NH + NN + 255) / 256, 256, 0, s_csr>>>(
        off_he, cur_he, bsum_he, off_nn, cur_nn, bsum_nn);
    fill2<<<gEdge, 256, 0, s_csr>>>(he_idx, node_idx, inc_vals,
                                    cur_he, src_he, w_he, cur_nn, src_nn, w_nn, NI);
    cudaEventRecord(evCsr, s_csr);

    // ---------------- main chain on default stream ----------------
    wtrans_enc<<<dim3(8, 4), dim3(32, 8)>>>(W_enc, wt);

    // encode both populations in one launch
    gemm_enc2<<<GNN + GNH, 256, SMEM_BYTES>>>(x_0, x_1, wt + WT_ENC, b_enc, x0h, x1h);

    const int spmm_he_blocks = (NH + 7) / 8;
    const int spmm_nn_blocks = (NN + 7) / 8;

    // ---------------- layer 0 ----------------
    cudaStreamWaitEvent(0, evWt, 0);    // msg weights ready
    gemm_h<128, false, false><<<GNN, 256, SMEM_BYTES>>>(
        x0h, x0h, nullptr, nullptr, wt + WT_MSG0, b_msg0, m0h, NN);
    cudaStreamWaitEvent(0, evCsr, 0);   // join: CSR needed from here on
    spmm_kernel<<<spmm_he_blocks, 256>>>(m0h, src_he, w_he, off_he, m0heA, NH);

    gemm_h<256, false, false><<<GNH, 256, SMEM_BYTES>>>(
        x1h, m0heA, nullptr, nullptr, wt + WT_MSG1, b_msg1, m1h, NH);
    spmm_kernel<<<spmm_nn_blocks, 256>>>(m1h, src_nn, w_nn, off_nn, m1nh, NN);

    // ---------------- layer 1 (residual updates fused into GEMM loaders) ----
    // m0 = sigm( u @ W ), u = sigm(x0 + m1n_L0); x0h <- u (needed by gemm_out)
    gemm_h<128, true, true><<<GNN, 256, SMEM_BYTES>>>(
        x0h, nullptr, m1nh, x0h, wt + WT_MSG0 + 16384, b_msg0 + 128, m0h, NN);
    spmm_kernel<<<spmm_he_blocks, 256>>>(m0h, src_he, w_he, off_he, m0heB, NH);

    // m1 = sigm( [sigm(x1 + m0he_L0) || m0he_L1] @ W ); no x1 writeback (dead)
    gemm_h<256, true, false><<<GNH, 256, SMEM_BYTES>>>(
        x1h, m0heB, m0heA, nullptr, wt + WT_MSG1 + 32768, b_msg1 + 128, m1h, NH);
    spmm_kernel<<<spmm_nn_blocks, 256>>>(m1h, src_nn, w_nn, off_nn, m1nh, NN);

    // out = sigm(x0 + m1n_L1) @ W_out + b_out
    gemm_out<<<(NN + 31) / 32, 256>>>(x0h, m1nh, W_out, b_out, out, NN);
}

// round 15
// speedup vs baseline: 1.1821x; 1.1821x over previous
#include <cuda_runtime.h>
#include <cuda_fp16.h>
#include <cstdint>

// Problem constants
#define NN 100000   // nodes
#define NH 50000    // hyperedges
#define NI 600000   // incidences
#define DH 128
#define NC 40

// ---------------- scratch (device globals) -----------------------------------
__device__ __align__(128) __half g_x0h   [NN * DH];
__device__ __align__(128) __half g_x1h   [NH * DH];
__device__ __align__(128) __half g_m0h   [NN * DH];
__device__ __align__(128) __half g_m0heA [NH * DH];   // L0 he-aggregate
__device__ __align__(128) __half g_m0heB [NH * DH];   // L1 he-aggregate
__device__ __align__(128) __half g_m1h   [NH * DH];
__device__ __align__(128) __half g_m1nh  [NN * DH];   // node-aggregate (reused)
__device__ __align__(128) __half g_wt    [131072];    // transposed fp16 weights
__device__ __align__(128) __half g_wto   [40 * 128];  // transposed fp16 W_out

// CSR scratch (both directions)
__device__ int   g_cnt_he[NH];
__device__ int   g_off_he[NH + 1];
__device__ int   g_cur_he[NH];
__device__ int   g_src_he[NI];
__device__ float g_w_he  [NI];
__device__ int   g_cnt_nn[NN];
__device__ int   g_off_nn[NN + 1];
__device__ int   g_cur_nn[NN];
__device__ int   g_src_nn[NI];
__device__ float g_w_nn  [NI];
__device__ int   g_bsum_he[128];
__device__ int   g_bsum_nn[128];

#define WT_ENC  0          // 128 x 256
#define WT_MSG0 32768      // 2 x (128 x 128)
#define WT_MSG1 65536      // 2 x (128 x 256)

__device__ __forceinline__ float sigm(float x) {
    return 1.0f / (1.0f + __expf(-x));
}

__device__ __forceinline__ void mma_f16(float (&d)[4], const uint32_t (&a)[4],
                                        const uint32_t (&b)[2]) {
    asm volatile(
        "mma.sync.aligned.m16n8k16.row.col.f32.f16.f16.f32 "
        "{%0,%1,%2,%3}, {%4,%5,%6,%7}, {%8,%9}, {%0,%1,%2,%3};"
        : "+f"(d[0]), "+f"(d[1]), "+f"(d[2]), "+f"(d[3])
        : "r"(a[0]), "r"(a[1]), "r"(a[2]), "r"(a[3]), "r"(b[0]), "r"(b[1]));
}

__device__ __forceinline__ void ldsm4(uint32_t (&r)[4], uint32_t addr) {
    asm volatile("ldmatrix.sync.aligned.m8n8.x4.shared.b16 {%0,%1,%2,%3}, [%4];"
        : "=r"(r[0]), "=r"(r[1]), "=r"(r[2]), "=r"(r[3]) : "r"(addr));
}

__device__ __forceinline__ void cp16(uint32_t dst, const void* src) {
    asm volatile("cp.async.cg.shared.global [%0], [%1], 16;"
                 :: "r"(dst), "l"(src));
}
__device__ __forceinline__ void cp16s(uint32_t dst, const void* src, int sz) {
    asm volatile("cp.async.cg.shared.global [%0], [%1], 16, %2;"
                 :: "r"(dst), "l"(src), "r"(sz));
}

// SMEM geometry: 3 stages, A and B tiles 128 rows x 32 halves, row stride 40 halves
#define STAGES 3
#define ASTR 40
#define STAGE_B (128 * ASTR * 2)            // 10240 bytes
#define SMEM_BYTES (STAGES * 2 * STAGE_B)   // 61440 bytes

// =================== MMA core =================================================
struct GemmCtx {
    uint32_t as0, bs0;
    int tid, lane, wid, wm, wn, block_row;
    uint32_t aaddr[2], baddr[4];
};

__device__ __forceinline__ void gemm_init(GemmCtx& g, uint32_t smem_u32,
                                          int block_row) {
    g.as0 = smem_u32;
    g.bs0 = smem_u32 + STAGES * STAGE_B;
    g.tid  = threadIdx.x;
    g.lane = g.tid & 31;
    g.wid  = g.tid >> 5;
    g.wm   = g.wid & 3;
    g.wn   = g.wid >> 2;
    g.block_row = block_row;
    const int arow_f = ((g.lane >> 3) & 1) * 8 + (g.lane & 7);
    const int akk_f  = (g.lane >> 4) * 8;
    const int brow_f = (g.lane >> 4) * 8 + (g.lane & 7);
    const int bkk_f  = ((g.lane >> 3) & 1) * 8;
    #pragma unroll
    for (int mi = 0; mi < 2; mi++)
        g.aaddr[mi] = g.as0 + ((g.wm * 32 + mi * 16 + arow_f) * ASTR + akk_f) * 2;
    #pragma unroll
    for (int nj = 0; nj < 4; nj++)
        g.baddr[nj] = g.bs0 + ((g.wn * 64 + nj * 16 + brow_f) * ASTR + bkk_f) * 2;
}

__device__ __forceinline__ void gemm_mma_chunk(const GemmCtx& g, int s,
                                               float (&acc)[2][8][4]) {
    #pragma unroll
    for (int ks = 0; ks < 2; ks++) {
        const uint32_t koff = s * STAGE_B + ks * 32;
        uint32_t af[2][4];
        ldsm4(af[0], g.aaddr[0] + koff);
        ldsm4(af[1], g.aaddr[1] + koff);
        uint32_t bf[4][4];
        #pragma unroll
        for (int nj = 0; nj < 4; nj++) ldsm4(bf[nj], g.baddr[nj] + koff);
        #pragma unroll
        for (int mi = 0; mi < 2; mi++)
            #pragma unroll
            for (int ni = 0; ni < 8; ni++) {
                uint32_t b[2] = { bf[ni >> 1][(ni & 1) * 2],
                                  bf[ni >> 1][(ni & 1) * 2 + 1] };
                mma_f16(acc[mi][ni], af[mi], b);
            }
    }
}

template<bool SIG>
__device__ __forceinline__ void gemm_epilogue_h(const GemmCtx& g, float (&acc)[2][8][4],
                                                const float* __restrict__ bias,
                                                __half* __restrict__ C, int M) {
    const int lr = g.lane >> 2, lc = g.lane & 3;
    #pragma unroll
    for (int mi = 0; mi < 2; mi++) {
        const int r0 = g.block_row + g.wm * 32 + mi * 16 + lr;
        #pragma unroll
        for (int ni = 0; ni < 8; ni++) {
            const int col = g.wn * 64 + ni * 8 + 2 * lc;
            const float b0 = bias[col], b1 = bias[col + 1];
            float v0 = acc[mi][ni][0] + b0;
            float v1 = acc[mi][ni][1] + b1;
            float v2 = acc[mi][ni][2] + b0;
            float v3 = acc[mi][ni][3] + b1;
            if (SIG) { v0 = sigm(v0); v1 = sigm(v1); v2 = sigm(v2); v3 = sigm(v3); }
            __half2 h01 = __floats2half2_rn(v0, v1);
            __half2 h23 = __floats2half2_rn(v2, v3);
            if (r0 < M)     *(__half2*)(C + (size_t)r0 * 128 + col) = h01;
            if (r0 + 8 < M) *(__half2*)(C + (size_t)(r0 + 8) * 128 + col) = h23;
        }
    }
}

// ---------------- fp16 GEMM with optional fused residual update --------------
// (R13 version: single-buffer FUSE loader)
template<int KTOT, bool FUSE, bool WB>
__global__ __launch_bounds__(256, 2)
void gemm_h(const __half* __restrict__ A0,
            const __half* __restrict__ A1,
            const __half* __restrict__ Madd,
            __half* __restrict__ Awb,
            const __half* __restrict__ Wt,
            const float* __restrict__ bias,
            __half* __restrict__ C, int M)
{
    extern __shared__ __half smem[];
    uint32_t smem_u32;
    asm("{ .reg .u64 t; cvta.to.shared.u64 t, %1; cvt.u32.u64 %0, t; }"
        : "=r"(smem_u32) : "l"(smem));
    GemmCtx g;
    gemm_init(g, smem_u32, blockIdx.x * 128);
    constexpr int NCHUNK = KTOT / 32;

    float acc[2][8][4];
    #pragma unroll
    for (int mi = 0; mi < 2; mi++)
        #pragma unroll
        for (int ni = 0; ni < 8; ni++)
            #pragma unroll
            for (int j = 0; j < 4; j++) acc[mi][ni][j] = 0.0f;

    uint4 px[2], pmh[2];

    auto ldgA = [&](int c) {
        if (!FUSE || c * 32 >= 128) return;
        #pragma unroll
        for (int i = 0; i < 2; i++) {
            const int idx = g.tid + i * 256;
            const int row = idx >> 2, seg = idx & 3;
            const int grow = g.block_row + row;
            const int col = c * 32 + seg * 8;
            if (grow < M) {
                px[i]  = *(const uint4*)(A0 + (size_t)grow * 128 + col);
                pmh[i] = *(const uint4*)(Madd + (size_t)grow * 128 + col);
            } else {
                px[i] = pmh[i] = make_uint4(0, 0, 0, 0);
            }
        }
    };
    auto stsA = [&](int c, int s) {
        if (!FUSE || c * 32 >= 128) return;
        #pragma unroll
        for (int i = 0; i < 2; i++) {
            const int idx = g.tid + i * 256;
            const int row = idx >> 2, seg = idx & 3;
            const int grow = g.block_row + row;
            const int col = c * 32 + seg * 8;
            const __half2* hx = reinterpret_cast<const __half2*>(&px[i]);
            const __half2* hm = reinterpret_cast<const __half2*>(&pmh[i]);
            uint4 h;
            uint32_t* hp = reinterpret_cast<uint32_t*>(&h);
            #pragma unroll
            for (int j = 0; j < 4; j++) {
                float2 fx = __half22float2(hx[j]);
                float2 fm = __half22float2(hm[j]);
                __half2 u = __floats2half2_rn(sigm(fx.x + fm.x), sigm(fx.y + fm.y));
                hp[j] = *reinterpret_cast<uint32_t*>(&u);
            }
            const uint32_t dst = g.as0 + s * STAGE_B + (row * ASTR + seg * 8) * 2;
            asm volatile("st.shared.v4.b32 [%0], {%1,%2,%3,%4};"
                         :: "r"(dst), "r"(h.x), "r"(h.y), "r"(h.z), "r"(h.w));
            if (WB && grow < M)
                *(uint4*)(Awb + (size_t)grow * 128 + col) = h;
        }
    };
    auto cpA = [&](int c, int s) {
        if (FUSE && c * 32 < 128) return;
        const int gk = c * 32;
        #pragma unroll
        for (int i = 0; i < 2; i++) {
            const int idx = g.tid + i * 256;
            const int row = idx >> 2, seg = idx & 3;
            const int grow = g.block_row + row;
            const int col = gk + seg * 8;
            const __half* src = (col < 128)
                ? A0 + (size_t)grow * 128 + col
                : A1 + (size_t)grow * 128 + (col - 128);
            const uint32_t dst = g.as0 + s * STAGE_B + (row * ASTR + seg * 8) * 2;
            cp16s(dst, grow < M ? (const void*)src : (const void*)Wt, grow < M ? 16 : 0);
        }
    };
    auto cpB = [&](int c, int s) {
        const int k0 = c * 32;
        #pragma unroll
        for (int i = 0; i < 2; i++) {
            const int idx = g.tid + i * 256;
            const int row = idx >> 2, seg = idx & 3;
            const uint32_t dst = g.bs0 + s * STAGE_B + (row * ASTR + seg * 8) * 2;
            cp16(dst, Wt + (size_t)row * KTOT + k0 + seg * 8);
        }
    };

    ldgA(0); cpA(0, 0); cpB(0, 0);
    asm volatile("cp.async.commit_group;");

    for (int c = 0; c < NCHUNK; c++) {
        const int s = c % 3;
        stsA(c, s);
        if (c + 1 < NCHUNK) {
            ldgA(c + 1);
            cpA(c + 1, (c + 1) % 3);
            cpB(c + 1, (c + 1) % 3);
            asm volatile("cp.async.commit_group;");
            asm volatile("cp.async.wait_group 1;");
        } else {
            asm volatile("cp.async.wait_group 0;");
        }
        __syncthreads();
        gemm_mma_chunk(g, s, acc);
    }
    gemm_epilogue_h<true>(g, acc, bias, C, M);
}

// ---------------- merged encode GEMM: both x_0 and x_1 in one launch ---------
#define GNN ((NN + 127) / 128)
#define GNH ((NH + 127) / 128)

__global__ __launch_bounds__(256, 2)
void gemm_enc2(const float* __restrict__ A_node,   // [NN,256] fp32
               const float* __restrict__ A_he,     // [NH,256] fp32
               const __half* __restrict__ Wt,      // [128][256]
               const float* __restrict__ bias,
               __half* __restrict__ C_node,
               __half* __restrict__ C_he)
{
    const bool isHE = blockIdx.x >= GNN;
    const int  bidx = isHE ? blockIdx.x - GNN : blockIdx.x;
    const float*  A = isHE ? A_he : A_node;
    __half*       C = isHE ? C_he : C_node;
    const int     M = isHE ? NH : NN;

    extern __shared__ __half smem[];
    uint32_t smem_u32;
    asm("{ .reg .u64 t; cvta.to.shared.u64 t, %1; cvt.u32.u64 %0, t; }"
        : "=r"(smem_u32) : "l"(smem));
    GemmCtx g;
    gemm_init(g, smem_u32, bidx * 128);
    constexpr int NCHUNK = 8;   // KTOT = 256

    const int arow = g.tid >> 1;
    const int aseg = g.tid & 1;
    const int grow = g.block_row + arow;

    float acc[2][8][4];
    #pragma unroll
    for (int mi = 0; mi < 2; mi++)
        #pragma unroll
        for (int ni = 0; ni < 8; ni++)
            #pragma unroll
            for (int j = 0; j < 4; j++) acc[mi][ni][j] = 0.0f;

    // depth-2 register prefetch for A (DRAM latency cover)
    float4 pa[2][4];
    auto ldgA = [&](int c, int buf) {
        const int gcol = c * 32 + aseg * 16;
        if (grow < M) {
            const float* p = A + (size_t)grow * 256 + gcol;
            #pragma unroll
            for (int j = 0; j < 4; j++) pa[buf][j] = *(const float4*)(p + 4 * j);
        } else {
            #pragma unroll
            for (int j = 0; j < 4; j++) pa[buf][j] = make_float4(0.f, 0.f, 0.f, 0.f);
        }
    };
    auto stsA = [&](int s, int buf) {
        uint32_t h[8];
        #pragma unroll
        for (int j = 0; j < 4; j++) {
            __half2 h0 = __floats2half2_rn(pa[buf][j].x, pa[buf][j].y);
            __half2 h1 = __floats2half2_rn(pa[buf][j].z, pa[buf][j].w);
            h[2 * j]     = *reinterpret_cast<uint32_t*>(&h0);
            h[2 * j + 1] = *reinterpret_cast<uint32_t*>(&h1);
        }
        const uint32_t dst = g.as0 + s * STAGE_B + (arow * ASTR + aseg * 16) * 2;
        asm volatile("st.shared.v4.b32 [%0], {%1,%2,%3,%4};"
                     :: "r"(dst), "r"(h[0]), "r"(h[1]), "r"(h[2]), "r"(h[3]));
        asm volatile("st.shared.v4.b32 [%0], {%1,%2,%3,%4};"
                     :: "r"(dst + 16), "r"(h[4]), "r"(h[5]), "r"(h[6]), "r"(h[7]));
    };
    auto cpB = [&](int c, int s) {
        const int k0 = c * 32;
        #pragma unroll
        for (int i = 0; i < 2; i++) {
            const int idx = g.tid + i * 256;
            const int row = idx >> 2, seg = idx & 3;
            const uint32_t dst = g.bs0 + s * STAGE_B + (row * ASTR + seg * 8) * 2;
            cp16(dst, Wt + (size_t)row * 256 + k0 + seg * 8);
        }
    };

    ldgA(0, 0);
    ldgA(1, 1);
    cpB(0, 0);
    asm volatile("cp.async.commit_group;");

    for (int c = 0; c < NCHUNK; c++) {
        const int s = c % 3;
        stsA(s, c & 1);
        if (c + 2 < NCHUNK) ldgA(c + 2, c & 1);
        if (c + 1 < NCHUNK) {
            cpB(c + 1, (c + 1) % 3);
            asm volatile("cp.async.commit_group;");
            asm volatile("cp.async.wait_group 1;");
        } else {
            asm volatile("cp.async.wait_group 0;");
        }
        __syncthreads();
        gemm_mma_chunk(g, s, acc);
    }
    gemm_epilogue_h<false>(g, acc, bias, C, M);
}

// ---------------- combined weight transpose+convert --------------------------
__global__ void wtrans_all(const float* __restrict__ W_enc,
                           const float* __restrict__ W_msg0,
                           const float* __restrict__ W_msg1,
                           __half* __restrict__ wt)
{
    const float* W; __half* Wt; int K;
    switch (blockIdx.z) {
        case 0: W = W_enc;           Wt = wt + WT_ENC;           K = 256; break;
        case 1: W = W_msg0;          Wt = wt + WT_MSG0;          K = 128; break;
        case 2: W = W_msg0 + 16384;  Wt = wt + WT_MSG0 + 16384;  K = 128; break;
        case 3: W = W_msg1;          Wt = wt + WT_MSG1;          K = 256; break;
        default:W = W_msg1 + 32768;  Wt = wt + WT_MSG1 + 32768;  K = 256; break;
    }
    const int kb = blockIdx.x * 32;
    if (kb >= K) return;
    const int nb = blockIdx.y * 32;

    __shared__ float tile[32][33];
    const int tx = threadIdx.x, ty = threadIdx.y;
    #pragma unroll
    for (int i = 0; i < 32; i += 8)
        tile[ty + i][tx] = W[(size_t)(kb + ty + i) * 128 + nb + tx];
    __syncthreads();
    #pragma unroll
    for (int i = 0; i < 32; i += 8)
        Wt[(size_t)(nb + ty + i) * K + kb + tx] = __float2half(tile[tx][ty + i]);
}

// ---------------- W_out transpose+convert: Wto[n][k] = (half)W[k][n] ---------
__global__ void wtrans_out(const float* __restrict__ W, __half* __restrict__ Wto)
{
    // 128 k x 40 n -> [40][128]; 5120 elems, one block of 256
    for (int i = threadIdx.x; i < 128 * 40; i += 256) {
        const int n = i / 128, k = i % 128;
        Wto[i] = __float2half(W[(size_t)k * 40 + n]);
    }
}

// ---------------- tensor-core output GEMM ------------------------------------
// C[M,40] = sigm(Ah + Mx) @ Wto^T + bias    (Wto fp16 [40][128])
#define OSTR 136
__global__ __launch_bounds__(256)
void gemm_out_tc(const __half* __restrict__ Ah, const __half* __restrict__ Mx,
                 const __half* __restrict__ Wto,
                 const float* __restrict__ bias, float* __restrict__ C, int M)
{
    __shared__ __half As[128][OSTR];
    __shared__ __half Bs[48][OSTR];

    uint32_t as_u32, bs_u32;
    asm("{ .reg .u64 t; cvta.to.shared.u64 t, %1; cvt.u32.u64 %0, t; }"
        : "=r"(as_u32) : "l"(&As[0][0]));
    asm("{ .reg .u64 t; cvta.to.shared.u64 t, %1; cvt.u32.u64 %0, t; }"
        : "=r"(bs_u32) : "l"(&Bs[0][0]));

    const int tid  = threadIdx.x;
    const int lane = tid & 31;
    const int wid  = tid >> 5;
    const int block_row = blockIdx.x * 128;

    // ---- stage A = sigm(Ah + Mx), fp16, 128 rows x 128 cols ----
    #pragma unroll
    for (int c = 0; c < 4; c++) {
        #pragma unroll
        for (int i = 0; i < 2; i++) {
            const int idx = tid + i * 256;
            const int row = idx >> 2, seg = idx & 3;
            const int grow = block_row + row;
            const int col = c * 32 + seg * 8;
            uint4 h = make_uint4(0, 0, 0, 0);
            if (grow < M) {
                uint4 hx = *(const uint4*)(Ah + (size_t)grow * 128 + col);
                uint4 hm = *(const uint4*)(Mx + (size_t)grow * 128 + col);
                const __half2* px = reinterpret_cast<const __half2*>(&hx);
                const __half2* pm = reinterpret_cast<const __half2*>(&hm);
                uint32_t* hp = reinterpret_cast<uint32_t*>(&h);
                #pragma unroll
                for (int j = 0; j < 4; j++) {
                    float2 fx = __half22float2(px[j]);
                    float2 fm = __half22float2(pm[j]);
                    __half2 u = __floats2half2_rn(sigm(fx.x + fm.x), sigm(fx.y + fm.y));
                    hp[j] = *reinterpret_cast<uint32_t*>(&u);
                }
            }
            *(uint4*)&As[row][col] = h;
        }
    }
    // ---- stage B: 40 valid rows + 8 zero rows, each 128 halves ----
    #pragma unroll
    for (int i = 0; i < 3; i++) {
        const int idx = tid + i * 256;   // 768 units of 8 halves: 48 rows x 16
        const int row = idx >> 4, seg = idx & 15;
        uint4 h = make_uint4(0, 0, 0, 0);
        if (row < 40) h = *(const uint4*)(Wto + (size_t)row * 128 + seg * 8);
        *(uint4*)&Bs[row][seg * 8] = h;
    }
    __syncthreads();

    // ---- MMA: each warp 16 rows x 40 cols (5 n8 frags of 6 staged) ----
    const int arow_f = ((lane >> 3) & 1) * 8 + (lane & 7);
    const int akk_f  = (lane >> 4) * 8;
    const int brow_f = (lane >> 4) * 8 + (lane & 7);
    const int bkk_f  = ((lane >> 3) & 1) * 8;
    const uint32_t aaddr = as_u32 + ((wid * 16 + arow_f) * OSTR + akk_f) * 2;
    uint32_t baddr[3];
    #pragma unroll
    for (int nj = 0; nj < 3; nj++)
        baddr[nj] = bs_u32 + ((nj * 16 + brow_f) * OSTR + bkk_f) * 2;

    float acc[5][4];
    #pragma unroll
    for (int ni = 0; ni < 5; ni++)
        #pragma unroll
        for (int j = 0; j < 4; j++) acc[ni][j] = 0.0f;

    #pragma unroll
    for (int k = 0; k < 8; k++) {
        const uint32_t koff = k * 32;   // 16 halves = 32 bytes
        uint32_t af[4];
        ldsm4(af, aaddr + koff);
        uint32_t bf[3][4];
        #pragma unroll
        for (int nj = 0; nj < 3; nj++) ldsm4(bf[nj], baddr[nj] + koff);
        #pragma unroll
        for (int ni = 0; ni < 5; ni++) {
            uint32_t b[2] = { bf[ni >> 1][(ni & 1) * 2],
                              bf[ni >> 1][(ni & 1) * 2 + 1] };
            mma_f16(acc[ni], af, b);
        }
    }

    // ---- epilogue: bias, fp32 out [M,40] ----
    const int lr = lane >> 2, lc = lane & 3;
    const int r0 = block_row + wid * 16 + lr;
    #pragma unroll
    for (int ni = 0; ni < 5; ni++) {
        const int col = ni * 8 + 2 * lc;
        const float b0 = bias[col], b1 = bias[col + 1];
        if (r0 < M)
            *(float2*)(C + (size_t)r0 * 40 + col) =
                make_float2(acc[ni][0] + b0, acc[ni][1] + b1);
        if (r0 + 8 < M)
            *(float2*)(C + (size_t)(r0 + 8) * 40 + col) =
                make_float2(acc[ni][2] + b0, acc[ni][3] + b1);
    }
}

// ---------------- CSR build (both directions fused) --------------------------
__global__ void hist2(const int* __restrict__ he, const int* __restrict__ nn,
                      int* __restrict__ cnt_he, int* __restrict__ cnt_nn, int n)
{
    int i = blockIdx.x * blockDim.x + threadIdx.x;
    if (i < n) {
        atomicAdd(&cnt_he[__ldg(he + i)], 1);
        atomicAdd(&cnt_nn[__ldg(nn + i)], 1);
    }
}

__device__ __forceinline__ void scan_blk_body(const int* cnt, int* off, int* bsum,
                                              int n, int bid)
{
    __shared__ int wsum[8];
    const int tid  = threadIdx.x;
    const int lane = tid & 31;
    const int base = bid * 2048 + tid * 8;

    int v[8];
    #pragma unroll
    for (int j = 0; j < 8; j++) v[j] = (base + j < n) ? __ldg(cnt + base + j) : 0;
    int s = 0;
    #pragma unroll
    for (int j = 0; j < 8; j++) { int t = v[j]; v[j] = s; s += t; }

    int ws = s;
    #pragma unroll
    for (int d = 1; d < 32; d <<= 1) {
        int t = __shfl_up_sync(0xffffffffu, ws, d);
        if (lane >= d) ws += t;
    }
    if (lane == 31) wsum[tid >> 5] = ws;
    __syncthreads();
    if (tid < 8) {
        int t = wsum[tid];
        int acc = t;
        #pragma unroll
        for (int d = 1; d < 8; d <<= 1) {
            int u = __shfl_up_sync(0xffu, acc, d);
            if (tid >= d) acc += u;
        }
        wsum[tid] = acc - t;
    }
    __syncthreads();

    const int thread_excl = (ws - s) + wsum[tid >> 5];
    #pragma unroll
    for (int j = 0; j < 8; j++)
        if (base + j < n) off[base + j] = thread_excl + v[j];
    if (tid == 255) bsum[bid] = thread_excl + s;
}

#define SB_HE ((NH + 2047) / 2048)   // 25
#define SB_NN ((NN + 2047) / 2048)   // 49

__global__ __launch_bounds__(256)
void scan_blk_both(const int* __restrict__ cnt_he, int* __restrict__ off_he,
                   int* __restrict__ bsum_he,
                   const int* __restrict__ cnt_nn, int* __restrict__ off_nn,
                   int* __restrict__ bsum_nn)
{
    if (blockIdx.x < SB_HE)
        scan_blk_body(cnt_he, off_he, bsum_he, NH, blockIdx.x);
    else
        scan_blk_body(cnt_nn, off_nn, bsum_nn, NN, blockIdx.x - SB_HE);
}

__global__ __launch_bounds__(128)
void scan_bsum2(int* __restrict__ bsum_he, int* __restrict__ bsum_nn)
{
    __shared__ int sm[128];
    int* b = (blockIdx.x == 0) ? bsum_he : bsum_nn;
    const int nb = (blockIdx.x == 0) ? SB_HE : SB_NN;
    const int tid = threadIdx.x;
    int v = (tid < nb) ? b[tid] : 0;
    sm[tid] = v;
    __syncthreads();
    for (int d = 1; d < 128; d <<= 1) {
        int t = (tid >= d) ? sm[tid - d] : 0;
        __syncthreads();
        sm[tid] += t;
        __syncthreads();
    }
    if (tid < nb) b[tid] = sm[tid] - v;
}

__global__ void scan_add_both(int* __restrict__ off_he, int* __restrict__ cur_he,
                              const int* __restrict__ bsum_he,
                              int* __restrict__ off_nn, int* __restrict__ cur_nn,
                              const int* __restrict__ bsum_nn)
{
    int i = blockIdx.x * blockDim.x + threadIdx.x;
    if (i < NH) {
        int v = off_he[i] + __ldg(bsum_he + (i >> 11));
        off_he[i] = v;
        cur_he[i] = v;
        if (i == 0) off_he[NH] = NI;
    } else if (i < NH + NN) {
        int j = i - NH;
        int v = off_nn[j] + __ldg(bsum_nn + (j >> 11));
        off_nn[j] = v;
        cur_nn[j] = v;
        if (j == 0) off_nn[NN] = NI;
    }
}

__global__ void fill2(const int* __restrict__ he, const int* __restrict__ nn,
                      const float* __restrict__ w,
                      int* __restrict__ cur_he, int* __restrict__ src_he,
                      float* __restrict__ w_he,
                      int* __restrict__ cur_nn, int* __restrict__ src_nn,
                      float* __restrict__ w_nn, int n)
{
    int i = blockIdx.x * blockDim.x + threadIdx.x;
    if (i >= n) return;
    const int h = __ldg(he + i);
    const int v = __ldg(nn + i);
    const float wv = __ldg(w + i);
    int p = atomicAdd(&cur_he[h], 1);
    src_he[p] = v;
    w_he[p]   = wv;
    int q = atomicAdd(&cur_nn[v], 1);
    src_nn[q] = h;
    w_nn[q]   = wv;
}

// ---------------- segment-sum SpMM: dst16 = sum_e w_e * src[csrc[e]] ---------
__global__ __launch_bounds__(256)
void spmm_kernel(const __half* __restrict__ src,
                 const int*    __restrict__ csrc,
                 const float*  __restrict__ cw,
                 const int*    __restrict__ off,
                 __half* __restrict__ dst16, int nrows)
{
    const int warp = (blockIdx.x * 256 + threadIdx.x) >> 5;
    const int lane = threadIdx.x & 31;
    if (warp >= nrows) return;

    const int s = __ldg(off + warp);
    const int e = __ldg(off + warp + 1);

    float a0 = 0.f, a1 = 0.f, a2 = 0.f, a3 = 0.f;
    int i = s;
    for (; i + 3 < e; i += 4) {
        int   n0 = __ldg(csrc + i),     n1 = __ldg(csrc + i + 1);
        int   n2 = __ldg(csrc + i + 2), n3 = __ldg(csrc + i + 3);
        float w0 = __ldg(cw + i),     w1 = __ldg(cw + i + 1);
        float w2 = __ldg(cw + i + 2), w3 = __ldg(cw + i + 3);
        uint2 p0 = *(const uint2*)(src + (size_t)n0 * 128 + lane * 4);
        uint2 p1 = *(const uint2*)(src + (size_t)n1 * 128 + lane * 4);
        uint2 p2 = *(const uint2*)(src + (size_t)n2 * 128 + lane * 4);
        uint2 p3 = *(const uint2*)(src + (size_t)n3 * 128 + lane * 4);
        float2 f0a = __half22float2(*(const __half2*)&p0.x);
        float2 f0b = __half22float2(*(const __half2*)&p0.y);
        float2 f1a = __half22float2(*(const __half2*)&p1.x);
        float2 f1b = __half22float2(*(const __half2*)&p1.y);
        float2 f2a = __half22float2(*(const __half2*)&p2.x);
        float2 f2b = __half22float2(*(const __half2*)&p2.y);
        float2 f3a = __half22float2(*(const __half2*)&p3.x);
        float2 f3b = __half22float2(*(const __half2*)&p3.y);
        a0 += w0 * f0a.x + w1 * f1a.x + w2 * f2a.x + w3 * f3a.x;
        a1 += w0 * f0a.y + w1 * f1a.y + w2 * f2a.y + w3 * f3a.y;
        a2 += w0 * f0b.x + w1 * f1b.x + w2 * f2b.x + w3 * f3b.x;
        a3 += w0 * f0b.y + w1 * f1b.y + w2 * f2b.y + w3 * f3b.y;
    }
    for (; i < e; i++) {
        const int   n0 = __ldg(csrc + i);
        const float w0 = __ldg(cw + i);
        const uint2 p0 = *(const uint2*)(src + (size_t)n0 * 128 + lane * 4);
        float2 f00 = __half22float2(*(const __half2*)&p0.x);
        float2 f01 = __half22float2(*(const __half2*)&p0.y);
        a0 += w0 * f00.x; a1 += w0 * f00.y;
        a2 += w0 * f01.x; a3 += w0 * f01.y;
    }
    __half2 h01 = __floats2half2_rn(a0, a1);
    __half2 h23 = __floats2half2_rn(a2, a3);
    uint2 u;
    u.x = *reinterpret_cast<uint32_t*>(&h01);
    u.y = *reinterpret_cast<uint32_t*>(&h23);
    *(uint2*)(dst16 + (size_t)warp * 128 + lane * 4) = u;
}

// ---------------- host driver ------------------------------------------------
extern "C" void kernel_launch(void* const* d_in, const int* in_sizes, int n_in,
                              void* d_out, int out_size)
{
    const float* x_0      = (const float*)d_in[0];
    const float* x_1      = (const float*)d_in[1];
    const int*   node_idx = (const int*)  d_in[2];
    const int*   he_idx   = (const int*)  d_in[3];
    const float* inc_vals = (const float*)d_in[4];
    const float* W_enc    = (const float*)d_in[5];
    const float* b_enc    = (const float*)d_in[6];
    const float* W_msg0   = (const float*)d_in[7];
    const float* b_msg0   = (const float*)d_in[8];
    const float* W_msg1   = (const float*)d_in[9];
    const float* b_msg1   = (const float*)d_in[10];
    const float* W_out    = (const float*)d_in[11];
    const float* b_out    = (const float*)d_in[12];
    float* out = (float*)d_out;

    __half *x0h, *x1h, *m0h, *m0heA, *m0heB, *m1h, *m1nh, *wt, *wto;
    int *cnt_he, *off_he, *cur_he, *src_he;
    int *cnt_nn, *off_nn, *cur_nn, *src_nn;
    int *bsum_he, *bsum_nn;
    float *w_he, *w_nn;
    cudaGetSymbolAddress((void**)&x0h,     g_x0h);
    cudaGetSymbolAddress((void**)&x1h,     g_x1h);
    cudaGetSymbolAddress((void**)&m0h,     g_m0h);
    cudaGetSymbolAddress((void**)&m0heA,   g_m0heA);
    cudaGetSymbolAddress((void**)&m0heB,   g_m0heB);
    cudaGetSymbolAddress((void**)&m1h,     g_m1h);
    cudaGetSymbolAddress((void**)&m1nh,    g_m1nh);
    cudaGetSymbolAddress((void**)&wt,      g_wt);
    cudaGetSymbolAddress((void**)&wto,     g_wto);
    cudaGetSymbolAddress((void**)&cnt_he,  g_cnt_he);
    cudaGetSymbolAddress((void**)&off_he,  g_off_he);
    cudaGetSymbolAddress((void**)&cur_he,  g_cur_he);
    cudaGetSymbolAddress((void**)&src_he,  g_src_he);
    cudaGetSymbolAddress((void**)&w_he,    g_w_he);
    cudaGetSymbolAddress((void**)&cnt_nn,  g_cnt_nn);
    cudaGetSymbolAddress((void**)&off_nn,  g_off_nn);
    cudaGetSymbolAddress((void**)&cur_nn,  g_cur_nn);
    cudaGetSymbolAddress((void**)&src_nn,  g_src_nn);
    cudaGetSymbolAddress((void**)&w_nn,    g_w_nn);
    cudaGetSymbolAddress((void**)&bsum_he, g_bsum_he);
    cudaGetSymbolAddress((void**)&bsum_nn, g_bsum_nn);

    static cudaStream_t s_csr = nullptr;
    static cudaEvent_t evFork = nullptr, evCsr = nullptr;
    static int smem_set = 0;
    if (!smem_set) {
        cudaFuncSetAttribute(gemm_enc2,
                             cudaFuncAttributeMaxDynamicSharedMemorySize, SMEM_BYTES);
        cudaFuncSetAttribute(gemm_h<128, false, false>,
                             cudaFuncAttributeMaxDynamicSharedMemorySize, SMEM_BYTES);
        cudaFuncSetAttribute(gemm_h<256, false, false>,
                             cudaFuncAttributeMaxDynamicSharedMemorySize, SMEM_BYTES);
        cudaFuncSetAttribute(gemm_h<128, true, true>,
                             cudaFuncAttributeMaxDynamicSharedMemorySize, SMEM_BYTES);
        cudaFuncSetAttribute(gemm_h<256, true, false>,
                             cudaFuncAttributeMaxDynamicSharedMemorySize, SMEM_BYTES);
        cudaStreamCreateWithFlags(&s_csr, cudaStreamNonBlocking);
        cudaEventCreateWithFlags(&evFork, cudaEventDisableTiming);
        cudaEventCreateWithFlags(&evCsr,  cudaEventDisableTiming);
        smem_set = 1;
    }

    const int gEdge = (NI + 255) / 256;

    // ---------------- fork: W_out transpose + CSR build on side stream -------
    cudaEventRecord(evFork, 0);
    cudaStreamWaitEvent(s_csr, evFork, 0);
    wtrans_out<<<1, 256, 0, s_csr>>>(W_out, wto);
    cudaMemsetAsync(cnt_he, 0, NH * sizeof(int), s_csr);
    cudaMemsetAsync(cnt_nn, 0, NN * sizeof(int), s_csr);
    hist2<<<gEdge, 256, 0, s_csr>>>(he_idx, node_idx, cnt_he, cnt_nn, NI);
    scan_blk_both<<<SB_HE + SB_NN, 256, 0, s_csr>>>(cnt_he, off_he, bsum_he,
                                                    cnt_nn, off_nn, bsum_nn);
    scan_bsum2<<<2, 128, 0, s_csr>>>(bsum_he, bsum_nn);
    scan_add_both<<<(NH + NN + 255) / 256, 256, 0, s_csr>>>(
        off_he, cur_he, bsum_he, off_nn, cur_nn, bsum_nn);
    fill2<<<gEdge, 256, 0, s_csr>>>(he_idx, node_idx, inc_vals,
                                    cur_he, src_he, w_he, cur_nn, src_nn, w_nn, NI);
    cudaEventRecord(evCsr, s_csr);

    // ---------------- main chain on default stream ----------------
    wtrans_all<<<dim3(8, 4, 5), dim3(32, 8)>>>(W_enc, W_msg0, W_msg1, wt);

    // encode both populations in one launch
    gemm_enc2<<<GNN + GNH, 256, SMEM_BYTES>>>(x_0, x_1, wt + WT_ENC, b_enc, x0h, x1h);

    const int spmm_he_blocks = (NH + 7) / 8;
    const int spmm_nn_blocks = (NN + 7) / 8;

    // ---------------- layer 0 ----------------
    gemm_h<128, false, false><<<GNN, 256, SMEM_BYTES>>>(
        x0h, x0h, nullptr, nullptr, wt + WT_MSG0, b_msg0, m0h, NN);
    cudaStreamWaitEvent(0, evCsr, 0);   // join: CSR (+wto) needed from here on
    spmm_kernel<<<spmm_he_blocks, 256>>>(m0h, src_he, w_he, off_he, m0heA, NH);

    gemm_h<256, false, false><<<GNH, 256, SMEM_BYTES>>>(
        x1h, m0heA, nullptr, nullptr, wt + WT_MSG1, b_msg1, m1h, NH);
    spmm_kernel<<<spmm_nn_blocks, 256>>>(m1h, src_nn, w_nn, off_nn, m1nh, NN);

    // ---------------- layer 1 (residual updates fused into GEMM loaders) ----
    gemm_h<128, true, true><<<GNN, 256, SMEM_BYTES>>>(
        x0h, nullptr, m1nh, x0h, wt + WT_MSG0 + 16384, b_msg0 + 128, m0h, NN);
    spmm_kernel<<<spmm_he_blocks, 256>>>(m0h, src_he, w_he, off_he, m0heB, NH);

    gemm_h<256, true, false><<<GNH, 256, SMEM_BYTES>>>(
        x1h, m0heB, m0heA, nullptr, wt + WT_MSG1 + 32768, b_msg1 + 128, m1h, NH);
    spmm_kernel<<<spmm_nn_blocks, 256>>>(m1h, src_nn, w_nn, off_nn, m1nh, NN);

    // out = sigm(x0 + m1n_L1) @ W_out + b_out   (tensor-core)
    gemm_out_tc<<<GNN, 256>>>(x0h, m1nh, wto, b_out, out, NN);
}